// round 4
// baseline (speedup 1.0000x reference)
#include <cuda_runtime.h>

#define B_DIM 128
#define C_DIM 2048
#define HW 196
#define NC 8
#define NM 4
#define NOUT 24                    // 8 A (m_c pre-bias) + 8 Z + 8 Y
#define PART_N (B_DIM * HW)        // 25088 global pixel-batch indices
#define SLABS 8
#define CSLAB (C_DIM / SLABS)      // 256

// ---- scratch (__device__ globals; no allocation allowed) ----
// slab-partial per-pixel outputs: [slab][out24][g]   (19.2 MB)
__device__ float g_part[SLABS * NOUT * PART_N];

// ---------------- packed f32x2 helpers ----------------
__device__ __forceinline__ unsigned long long fma2(
    unsigned long long a, unsigned long long b, unsigned long long c) {
    unsigned long long d;
    asm("fma.rn.f32x2 %0, %1, %2, %3;" : "=l"(d) : "l"(a), "l"(b), "l"(c));
    return d;
}
__device__ __forceinline__ unsigned long long dup2(float v) {
    unsigned long long d;
    asm("mov.b64 %0, {%1, %2};" : "=l"(d) : "f"(v), "f"(v));
    return d;
}
__device__ __forceinline__ void unpack2(unsigned long long v, float& lo, float& hi) {
    asm("mov.b64 {%0, %1}, %2;" : "=f"(lo), "=f"(hi) : "l"(v));
}

// ============================================================================
// K1: fused streaming pass with inline weight prep.
// grid (98, 8), 256 threads, up to 4 blocks/SM.
// Block stages its 256-channel weight slab (24 floats/channel) into smem
// directly from w_down/w_cls (L2-hot), then each thread owns one global
// pixel-batch index g and accumulates 24 outputs (A=w_eff*x, Z=w_cls_lo*x,
// Y=w_cls_hi*x) over the slab's 256 channels with packed f32x2 FMA.
// ============================================================================
__global__ void __launch_bounds__(256, 4) k1_main(
    const float* __restrict__ x,
    const float* __restrict__ w_down,
    const float* __restrict__ w_cls) {
    __shared__ float wsh[CSLAB * NOUT];   // 24 KB

    const int slab = blockIdx.y;
    const int t = threadIdx.x;

    // ---- inline weight prep: thread t owns local channel t ----
    {
        const int cg = slab * CSLAB + t;
        float* w = &wsh[t * NOUT];
#pragma unroll
        for (int k = 0; k < NC; ++k) {
            float s0 = w_down[(k * NM + 0) * C_DIM + cg];
            float s1 = w_down[(k * NM + 1) * C_DIM + cg];
            float s2 = w_down[(k * NM + 2) * C_DIM + cg];
            float s3 = w_down[(k * NM + 3) * C_DIM + cg];
            w[k]      = 0.25f * ((s0 + s1) + (s2 + s3));
            w[8 + k]  = w_cls[k * 2 * C_DIM + cg];
            w[16 + k] = w_cls[k * 2 * C_DIM + C_DIM + cg];
        }
    }
    __syncthreads();

    const int g = blockIdx.x * 256 + t;
    const int b = g / HW;
    const int p = g - b * HW;

    unsigned long long acc[12];
#pragma unroll
    for (int j = 0; j < 12; ++j) acc[j] = dup2(0.f);

    const float* xp = x + (size_t)b * C_DIM * HW + (size_t)(slab * CSLAB) * HW + p;

#pragma unroll 2
    for (int c0 = 0; c0 < CSLAB; c0 += 8) {
        // front-batch 8 independent global loads
        float xv[8];
#pragma unroll
        for (int u = 0; u < 8; ++u) xv[u] = __ldg(&xp[(c0 + u) * HW]);
#pragma unroll
        for (int u = 0; u < 8; ++u) {
            unsigned long long xx = dup2(xv[u]);
            const ulonglong2* w = (const ulonglong2*)&wsh[(c0 + u) * NOUT];
            ulonglong2 w0 = w[0];
            ulonglong2 w1 = w[1];
            ulonglong2 w2 = w[2];
            acc[0]  = fma2(xx, w0.x, acc[0]);
            acc[1]  = fma2(xx, w0.y, acc[1]);
            acc[2]  = fma2(xx, w1.x, acc[2]);
            acc[3]  = fma2(xx, w1.y, acc[3]);
            acc[4]  = fma2(xx, w2.x, acc[4]);
            acc[5]  = fma2(xx, w2.y, acc[5]);
            ulonglong2 w3 = w[3];
            ulonglong2 w4 = w[4];
            ulonglong2 w5 = w[5];
            acc[6]  = fma2(xx, w3.x, acc[6]);
            acc[7]  = fma2(xx, w3.y, acc[7]);
            acc[8]  = fma2(xx, w4.x, acc[8]);
            acc[9]  = fma2(xx, w4.y, acc[9]);
            acc[10] = fma2(xx, w5.x, acc[10]);
            acc[11] = fma2(xx, w5.y, acc[11]);
        }
    }

    // write 24 slab-partials, coalesced per output row
    float* base = &g_part[(size_t)slab * NOUT * PART_N + g];
#pragma unroll
    for (int j = 0; j < 12; ++j) {
        float lo, hi;
        unpack2(acc[j], lo, hi);
        base[(2 * j) * PART_N]     = lo;
        base[(2 * j + 1) * PART_N] = hi;
    }
}

// ============================================================================
// K2: per-batch epilogue. 128 blocks x 224 threads (196 active pixels).
//   m_c[k,p] = sum_s A_part + beff[k]   -> out_mc, smem
//   v[k] = mean_p m_c                    -> out_v
//   m[p] = (1/8) sum_k v[k] m_c[k,p]     -> out_m
//   output[k] = (1/HW) sum_p (Z[k,p] + m[p]*Y[k,p]) + b_cls[k]
// ============================================================================
__global__ void __launch_bounds__(224) k2_epi(
    const float* __restrict__ b_down,
    const float* __restrict__ b_cls,
    float* __restrict__ out_v,
    float* __restrict__ out_output,
    float* __restrict__ out_m,
    float* __restrict__ out_mc) {
    __shared__ float red[NC * 200];   // m_c staging, padded rows
    __shared__ float vsh[NC];
    __shared__ float besh[NC];
    __shared__ float wpart[7][NC];

    const int b = blockIdx.x;
    const int t = threadIdx.x;
    const int g0 = b * HW;

    if (t < NC)
        besh[t] = 0.25f * (b_down[4 * t] + b_down[4 * t + 1] +
                           b_down[4 * t + 2] + b_down[4 * t + 3]);
    __syncthreads();

    if (t < HW) {
#pragma unroll
        for (int k = 0; k < NC; ++k) {
            float a = 0.f;
#pragma unroll
            for (int s = 0; s < SLABS; ++s)
                a += g_part[((size_t)s * NOUT + k) * PART_N + g0 + t];
            float mc = a + besh[k];
            red[k * 200 + t] = mc;
            out_mc[((size_t)b * NC + k) * HW + t] = mc;
        }
    }
    __syncthreads();

    if (t < NC) {
        float s = 0.f;
        for (int p = 0; p < HW; ++p) s += red[t * 200 + p];
        float vv = s * (1.0f / (float)HW);
        vsh[t] = vv;
        out_v[b * NC + t] = vv;
    }
    __syncthreads();

    float m = 0.f;
    if (t < HW) {
#pragma unroll
        for (int k = 0; k < NC; ++k) m = fmaf(vsh[k], red[k * 200 + t], m);
        m *= (1.0f / (float)NC);
        out_m[b * HW + t] = m;
    }

    // per-thread partial of output: Z + m*Y
    float po[NC];
#pragma unroll
    for (int k = 0; k < NC; ++k) po[k] = 0.f;
    if (t < HW) {
#pragma unroll
        for (int k = 0; k < NC; ++k) {
            float z = 0.f, y = 0.f;
#pragma unroll
            for (int s = 0; s < SLABS; ++s) {
                z += g_part[((size_t)s * NOUT + 8 + k) * PART_N + g0 + t];
                y += g_part[((size_t)s * NOUT + 16 + k) * PART_N + g0 + t];
            }
            po[k] = z + m * y;
        }
    }
#pragma unroll
    for (int o = 16; o; o >>= 1) {
#pragma unroll
        for (int k = 0; k < NC; ++k)
            po[k] += __shfl_down_sync(0xffffffffu, po[k], o);
    }
    const int lane = t & 31, warp = t >> 5;
    if (lane == 0) {
#pragma unroll
        for (int k = 0; k < NC; ++k) wpart[warp][k] = po[k];
    }
    __syncthreads();
    if (t < NC) {
        float s = 0.f;
#pragma unroll
        for (int w = 0; w < 7; ++w) s += wpart[w][t];
        out_output[b * NC + t] = s * (1.0f / (float)HW) + b_cls[t];
    }
}

// ============================================================================
// kernel_launch: 2 launches, graph-capturable, deterministic.
// Output layout: v[128,8]@0, output[128,8]@1024, m[128,196]@2048,
//                m_c[128,8,196]@27136.
// ============================================================================
extern "C" void kernel_launch(void* const* d_in, const int* in_sizes, int n_in,
                              void* d_out, int out_size) {
    const float* x      = (const float*)d_in[0];
    const float* w_down = (const float*)d_in[1];
    const float* b_down = (const float*)d_in[2];
    const float* w_cls  = (const float*)d_in[3];
    const float* b_cls  = (const float*)d_in[4];

    float* out        = (float*)d_out;
    float* out_v      = out;
    float* out_output = out + 1024;
    float* out_m      = out + 2048;
    float* out_mc     = out + 27136;

    k1_main<<<dim3(PART_N / 256, SLABS), 256>>>(x, w_down, w_cls);
    k2_epi<<<B_DIM, 224>>>(b_down, b_cls, out_v, out_output, out_m, out_mc);
}

// round 5
// speedup vs baseline: 1.0560x; 1.0560x over previous
#include <cuda_runtime.h>

#define B_DIM 128
#define C_DIM 2048
#define HW 196
#define NC 8
#define NM 4
#define PART_N (B_DIM * HW)        // 25088
#define SLABS 8
#define CSLAB (C_DIM / SLABS)      // 256

// ---- scratch (__device__ globals; no allocation allowed) ----
__device__ float g_part[SLABS * NC * PART_N];   // A slab-partials, 6.4 MB
__device__ float g_gapx[B_DIM * C_DIM];         // (1/HW) sum_p x
__device__ float g_gapu[B_DIM * C_DIM];         // (1/HW) sum_p m*x
__device__ float g_dummy;

// ---------------- packed f32x2 helpers ----------------
__device__ __forceinline__ unsigned long long fma2(
    unsigned long long a, unsigned long long b, unsigned long long c) {
    unsigned long long d;
    asm("fma.rn.f32x2 %0, %1, %2, %3;" : "=l"(d) : "l"(a), "l"(b), "l"(c));
    return d;
}
__device__ __forceinline__ unsigned long long dup2(float v) {
    unsigned long long d;
    asm("mov.b64 %0, {%1, %2};" : "=l"(d) : "f"(v), "f"(v));
    return d;
}
__device__ __forceinline__ void unpack2(unsigned long long v, float& lo, float& hi) {
    asm("mov.b64 {%0, %1}, %2;" : "=f"(lo), "=f"(hi) : "l"(v));
}

// ============================================================================
// K1: per-pixel A maps only. grid (98, 8), 256 threads.
// Thread owns pixel-batch index g; 8 accumulators (4 packed) over 256
// channels of its slab. Inline weight fold into smem (8 KB).
// ============================================================================
__global__ void __launch_bounds__(256, 4) k1_main(
    const float* __restrict__ x,
    const float* __restrict__ w_down) {
    __shared__ float wsh[CSLAB * NC];   // 8 KB

    const int slab = blockIdx.y;
    const int t = threadIdx.x;

    // inline weight fold: thread t owns local channel t
    {
        const int cg = slab * CSLAB + t;
        float* w = &wsh[t * NC];
#pragma unroll
        for (int k = 0; k < NC; ++k) {
            float s0 = w_down[(k * NM + 0) * C_DIM + cg];
            float s1 = w_down[(k * NM + 1) * C_DIM + cg];
            float s2 = w_down[(k * NM + 2) * C_DIM + cg];
            float s3 = w_down[(k * NM + 3) * C_DIM + cg];
            w[k] = 0.25f * ((s0 + s1) + (s2 + s3));
        }
    }
    __syncthreads();

    const int g = blockIdx.x * 256 + t;
    const int b = g / HW;
    const int p = g - b * HW;

    unsigned long long acc[4];
#pragma unroll
    for (int j = 0; j < 4; ++j) acc[j] = dup2(0.f);

    const float* xp = x + (size_t)b * C_DIM * HW + (size_t)(slab * CSLAB) * HW + p;

#pragma unroll 2
    for (int c0 = 0; c0 < CSLAB; c0 += 8) {
        float xv[8];
#pragma unroll
        for (int u = 0; u < 8; ++u) xv[u] = __ldg(&xp[(c0 + u) * HW]);
#pragma unroll
        for (int u = 0; u < 8; ++u) {
            unsigned long long xx = dup2(xv[u]);
            const ulonglong2* w = (const ulonglong2*)&wsh[(c0 + u) * NC];
            ulonglong2 w0 = w[0];
            ulonglong2 w1 = w[1];
            acc[0] = fma2(xx, w0.x, acc[0]);
            acc[1] = fma2(xx, w0.y, acc[1]);
            acc[2] = fma2(xx, w1.x, acc[2]);
            acc[3] = fma2(xx, w1.y, acc[3]);
        }
    }

    float* base = &g_part[(size_t)slab * NC * PART_N + g];
#pragma unroll
    for (int j = 0; j < 4; ++j) {
        float lo, hi;
        unpack2(acc[j], lo, hi);
        base[(2 * j) * PART_N]     = lo;
        base[(2 * j + 1) * PART_N] = hi;
    }
}

// ============================================================================
// K2: per-batch epilogue for pass 1. 128 blocks x 224 threads.
//   m_c[k,p] = sum_s A_part + beff[k]; v[k] = mean_p m_c;
//   m[p] = (1/8) sum_k v[k]*m_c[k,p]
// ============================================================================
__global__ void __launch_bounds__(224) k2_epi(
    const float* __restrict__ b_down,
    float* __restrict__ out_v,
    float* __restrict__ out_m,
    float* __restrict__ out_mc) {
    __shared__ float red[NC * 200];
    __shared__ float vsh[NC];
    __shared__ float besh[NC];

    const int b = blockIdx.x;
    const int t = threadIdx.x;
    const int g0 = b * HW;

    if (t < NC)
        besh[t] = 0.25f * (b_down[4 * t] + b_down[4 * t + 1] +
                           b_down[4 * t + 2] + b_down[4 * t + 3]);
    __syncthreads();

    if (t < HW) {
#pragma unroll
        for (int k = 0; k < NC; ++k) {
            float a = 0.f;
#pragma unroll
            for (int s = 0; s < SLABS; ++s)
                a += g_part[((size_t)s * NC + k) * PART_N + g0 + t];
            float mc = a + besh[k];
            red[k * 200 + t] = mc;
            out_mc[((size_t)b * NC + k) * HW + t] = mc;
        }
    }
    __syncthreads();

    if (t < NC) {
        float s = 0.f;
        for (int p = 0; p < HW; ++p) s += red[t * 200 + p];
        float vv = s * (1.0f / (float)HW);
        vsh[t] = vv;
        out_v[b * NC + t] = vv;
    }
    __syncthreads();

    if (t < HW) {
        float m = 0.f;
#pragma unroll
        for (int k = 0; k < NC; ++k) m = fmaf(vsh[k], red[k * 200 + t], m);
        out_m[b * HW + t] = m * (1.0f / (float)NC);
    }
}

// ============================================================================
// K3: second streaming x pass — dense float4, warp-per-row.
// grid (C/8=256, B=128), 256 threads (8 warps; warp w -> channel bx*8+w).
//   gapx[b,c] = (1/HW) sum_p x ; gapu[b,c] = (1/HW) sum_p m[p]*x
// ============================================================================
__global__ void __launch_bounds__(256) k3_gap(
    const float* __restrict__ x,
    const float* __restrict__ m_in) {
    __shared__ float4 msh4[49];

    const int b = blockIdx.y;
    const int t = threadIdx.x;
    if (t < 49) msh4[t] = ((const float4*)(m_in + b * HW))[t];
    __syncthreads();

    const int w = t >> 5, l = t & 31;
    const int c = blockIdx.x * 8 + w;
    const float4* row = (const float4*)(x + ((size_t)b * C_DIM + c) * HW);

    float4 xa = row[l];
    float4 ma = msh4[l];
    float s1 = ((xa.x + xa.y) + (xa.z + xa.w));
    float s2 = fmaf(xa.x, ma.x, fmaf(xa.y, ma.y, fmaf(xa.z, ma.z, xa.w * ma.w)));
    if (l < 17) {
        float4 xb = row[l + 32];
        float4 mb = msh4[l + 32];
        s1 += ((xb.x + xb.y) + (xb.z + xb.w));
        s2 = fmaf(xb.x, mb.x, fmaf(xb.y, mb.y, fmaf(xb.z, mb.z, fmaf(xb.w, mb.w, s2))));
    }
#pragma unroll
    for (int o = 16; o; o >>= 1) {
        s1 += __shfl_down_sync(0xffffffffu, s1, o);
        s2 += __shfl_down_sync(0xffffffffu, s2, o);
    }
    if (l == 0) {
        g_gapx[b * C_DIM + c] = s1 * (1.0f / (float)HW);
        g_gapu[b * C_DIM + c] = s2 * (1.0f / (float)HW);
    }
}

// ============================================================================
// K4: output[b,k] = sum_c (w_lo[k,c]*gapx[b,c] + w_hi[k,c]*gapu[b,c]) + b_cls
// One block per batch, 256 threads.
// ============================================================================
__global__ void __launch_bounds__(256) k4_out(
    const float* __restrict__ w_cls,
    const float* __restrict__ b_cls,
    float* __restrict__ out_output) {
    const int b = blockIdx.x;
    const int t = threadIdx.x;
    const int lane = t & 31, warp = t >> 5;

    float acc[NC];
#pragma unroll
    for (int k = 0; k < NC; ++k) acc[k] = 0.f;

#pragma unroll 1
    for (int c = t; c < C_DIM; c += 256) {
        float gx = g_gapx[b * C_DIM + c];
        float gu = g_gapu[b * C_DIM + c];
#pragma unroll
        for (int k = 0; k < NC; ++k) {
            acc[k] = fmaf(gx, w_cls[k * 2 * C_DIM + c], acc[k]);
            acc[k] = fmaf(gu, w_cls[k * 2 * C_DIM + C_DIM + c], acc[k]);
        }
    }
#pragma unroll
    for (int o = 16; o; o >>= 1) {
#pragma unroll
        for (int k = 0; k < NC; ++k)
            acc[k] += __shfl_down_sync(0xffffffffu, acc[k], o);
    }
    __shared__ float part[8][NC];
    if (lane == 0) {
#pragma unroll
        for (int k = 0; k < NC; ++k) part[warp][k] = acc[k];
    }
    __syncthreads();
    if (t < NC) {
        float s = b_cls[t];
#pragma unroll
        for (int w2 = 0; w2 < 8; ++w2) s += part[w2][t];
        out_output[b * NC + t] = s;
    }
}

// K5: no-op pad so each kernel_launch = 5 launches -> ncu -s 5 lands on K1.
__global__ void k5_pad() { if (threadIdx.x == 0) g_dummy = 0.f; }

// ============================================================================
// Output layout: v[128,8]@0, output[128,8]@1024, m[128,196]@2048,
//                m_c[128,8,196]@27136.
// ============================================================================
extern "C" void kernel_launch(void* const* d_in, const int* in_sizes, int n_in,
                              void* d_out, int out_size) {
    const float* x      = (const float*)d_in[0];
    const float* w_down = (const float*)d_in[1];
    const float* b_down = (const float*)d_in[2];
    const float* w_cls  = (const float*)d_in[3];
    const float* b_cls  = (const float*)d_in[4];

    float* out        = (float*)d_out;
    float* out_v      = out;
    float* out_output = out + 1024;
    float* out_m      = out + 2048;
    float* out_mc     = out + 27136;

    k1_main<<<dim3(PART_N / 256, SLABS), 256>>>(x, w_down);
    k2_epi<<<B_DIM, 224>>>(b_down, out_v, out_m, out_mc);
    k3_gap<<<dim3(C_DIM / 8, B_DIM), 256>>>(x, out_m);
    k4_out<<<B_DIM, 256>>>(w_cls, b_cls, out_output);
    k5_pad<<<1, 32>>>();
}

// round 6
// speedup vs baseline: 1.2841x; 1.2161x over previous
#include <cuda_runtime.h>

#define B_DIM 128
#define C_DIM 2048
#define HW 196
#define NC 8
#define NM 4
#define PART_N (B_DIM * HW)        // 25088
#define SLABS 8
#define CSLAB (C_DIM / SLABS)      // 256
#define NGRP 64                    // channel groups of 32 for pass 2

// ---- scratch (__device__ globals; no allocation allowed) ----
__device__ float g_part[SLABS * NC * PART_N];   // A slab-partials, 6.4 MB
__device__ float g_po[B_DIM * NGRP * NC];       // per-group output partials, 256 KB

// ---------------- packed f32x2 helpers ----------------
__device__ __forceinline__ unsigned long long fma2(
    unsigned long long a, unsigned long long b, unsigned long long c) {
    unsigned long long d;
    asm("fma.rn.f32x2 %0, %1, %2, %3;" : "=l"(d) : "l"(a), "l"(b), "l"(c));
    return d;
}
__device__ __forceinline__ unsigned long long dup2(float v) {
    unsigned long long d;
    asm("mov.b64 %0, {%1, %2};" : "=l"(d) : "f"(v), "f"(v));
    return d;
}
__device__ __forceinline__ void unpack2(unsigned long long v, float& lo, float& hi) {
    asm("mov.b64 {%0, %1}, %2;" : "=f"(lo), "=f"(hi) : "l"(v));
}

// ============================================================================
// K1: per-pixel A maps. grid (98, 8), 256 threads, 4 blocks/SM.
// 16-channel LDG batches: ~130 issued instructions per batch fully cover
// the ~600-cycle DRAM latency at 8 warps/SMSP.
// ============================================================================
__global__ void __launch_bounds__(256, 4) k1_main(
    const float* __restrict__ x,
    const float* __restrict__ w_down) {
    __shared__ float wsh[CSLAB * NC];   // 8 KB

    const int slab = blockIdx.y;
    const int t = threadIdx.x;

    // inline weight fold: thread t owns local channel t
    {
        const int cg = slab * CSLAB + t;
        float* w = &wsh[t * NC];
#pragma unroll
        for (int k = 0; k < NC; ++k) {
            float s0 = w_down[(k * NM + 0) * C_DIM + cg];
            float s1 = w_down[(k * NM + 1) * C_DIM + cg];
            float s2 = w_down[(k * NM + 2) * C_DIM + cg];
            float s3 = w_down[(k * NM + 3) * C_DIM + cg];
            w[k] = 0.25f * ((s0 + s1) + (s2 + s3));
        }
    }
    __syncthreads();

    const int g = blockIdx.x * 256 + t;
    const int b = g / HW;
    const int p = g - b * HW;

    unsigned long long acc[4];
#pragma unroll
    for (int j = 0; j < 4; ++j) acc[j] = dup2(0.f);

    const float* xp = x + (size_t)b * C_DIM * HW + (size_t)(slab * CSLAB) * HW + p;

#pragma unroll 1
    for (int c0 = 0; c0 < CSLAB; c0 += 16) {
        // front-batch 16 independent global loads (MLP = 16)
        float xv[16];
#pragma unroll
        for (int u = 0; u < 16; ++u) xv[u] = __ldg(&xp[(c0 + u) * HW]);
#pragma unroll
        for (int u = 0; u < 16; ++u) {
            unsigned long long xx = dup2(xv[u]);
            const ulonglong2* w = (const ulonglong2*)&wsh[(c0 + u) * NC];
            ulonglong2 w0 = w[0];
            ulonglong2 w1 = w[1];
            acc[0] = fma2(xx, w0.x, acc[0]);
            acc[1] = fma2(xx, w0.y, acc[1]);
            acc[2] = fma2(xx, w1.x, acc[2]);
            acc[3] = fma2(xx, w1.y, acc[3]);
        }
    }

    float* base = &g_part[(size_t)slab * NC * PART_N + g];
#pragma unroll
    for (int j = 0; j < 4; ++j) {
        float lo, hi;
        unpack2(acc[j], lo, hi);
        base[(2 * j) * PART_N]     = lo;
        base[(2 * j + 1) * PART_N] = hi;
    }
}

// ============================================================================
// K2: per-batch epilogue for pass 1. 128 blocks x 224 threads.
//   m_c[k,p] = sum_s A_part + beff[k]; v[k] = mean_p m_c;
//   m[p] = (1/8) sum_k v[k]*m_c[k,p]
// ============================================================================
__global__ void __launch_bounds__(224) k2_epi(
    const float* __restrict__ b_down,
    float* __restrict__ out_v,
    float* __restrict__ out_m,
    float* __restrict__ out_mc) {
    __shared__ float red[NC * 200];
    __shared__ float vsh[NC];
    __shared__ float besh[NC];

    const int b = blockIdx.x;
    const int t = threadIdx.x;
    const int g0 = b * HW;

    if (t < NC)
        besh[t] = 0.25f * (b_down[4 * t] + b_down[4 * t + 1] +
                           b_down[4 * t + 2] + b_down[4 * t + 3]);
    __syncthreads();

    if (t < HW) {
        // front-batch all 64 partial loads in groups of 8 (per-k)
#pragma unroll
        for (int k = 0; k < NC; ++k) {
            float a[SLABS];
#pragma unroll
            for (int s = 0; s < SLABS; ++s)
                a[s] = g_part[((size_t)s * NC + k) * PART_N + g0 + t];
            float sum = ((a[0] + a[1]) + (a[2] + a[3])) +
                        ((a[4] + a[5]) + (a[6] + a[7]));
            float mc = sum + besh[k];
            red[k * 200 + t] = mc;
            out_mc[((size_t)b * NC + k) * HW + t] = mc;
        }
    }
    __syncthreads();

    if (t < NC) {
        float s = 0.f;
        for (int p = 0; p < HW; ++p) s += red[t * 200 + p];
        float vv = s * (1.0f / (float)HW);
        vsh[t] = vv;
        out_v[b * NC + t] = vv;
    }
    __syncthreads();

    if (t < HW) {
        float m = 0.f;
#pragma unroll
        for (int k = 0; k < NC; ++k) m = fmaf(vsh[k], red[k * 200 + t], m);
        out_m[b * HW + t] = m * (1.0f / (float)NC);
    }
}

// ============================================================================
// K3: second streaming x pass, fused with the output dot-product.
// grid (NGRP=64, B=128), 256 threads (8 warps). Warp w owns 4 channels of
// the block's 32-channel group; all 8 row-LDG.128s issued up front (MLP 8).
// Per channel: gx = (1/HW) sum_p x, gu = (1/HW) sum_p m*x  (warp reduce).
// Then the block folds its 32 channels into po[k] = sum_c w_lo*gx + w_hi*gu
// (warp k reduces over 32 lanes=channels) -> g_po[b][grp][k]. gapx/gapu
// never touch gmem.
// ============================================================================
__global__ void __launch_bounds__(256) k3_gap(
    const float* __restrict__ x,
    const float* __restrict__ m_in,
    const float* __restrict__ w_cls) {
    __shared__ float4 msh4[49];
    __shared__ float gxs[32];
    __shared__ float gus[32];

    const int b = blockIdx.y;
    const int grp = blockIdx.x;
    const int t = threadIdx.x;
    const int w = t >> 5, l = t & 31;

    if (t < 49) msh4[t] = ((const float4*)(m_in + b * HW))[t];
    __syncthreads();

    const int cbase = grp * 32 + w * 4;
    const float* rowb = x + ((size_t)b * C_DIM + cbase) * HW;
    const bool tail = (l < 17);

    // front-load 8 LDG.128 (4 channels x 2 segments)
    float4 xa[4], xb[4];
#pragma unroll
    for (int i = 0; i < 4; ++i)
        xa[i] = ((const float4*)(rowb + i * HW))[l];
#pragma unroll
    for (int i = 0; i < 4; ++i)
        xb[i] = tail ? ((const float4*)(rowb + i * HW))[l + 32]
                     : make_float4(0.f, 0.f, 0.f, 0.f);

    float4 ma = msh4[l];
    float4 mb = tail ? msh4[l + 32] : make_float4(0.f, 0.f, 0.f, 0.f);

#pragma unroll
    for (int i = 0; i < 4; ++i) {
        float s1 = ((xa[i].x + xa[i].y) + (xa[i].z + xa[i].w)) +
                   ((xb[i].x + xb[i].y) + (xb[i].z + xb[i].w));
        float s2 = fmaf(xa[i].x, ma.x, fmaf(xa[i].y, ma.y,
                   fmaf(xa[i].z, ma.z, xa[i].w * ma.w)));
        s2 = fmaf(xb[i].x, mb.x, fmaf(xb[i].y, mb.y,
             fmaf(xb[i].z, mb.z, fmaf(xb[i].w, mb.w, s2))));
#pragma unroll
        for (int o = 16; o; o >>= 1) {
            s1 += __shfl_xor_sync(0xffffffffu, s1, o);
            s2 += __shfl_xor_sync(0xffffffffu, s2, o);
        }
        if (l == 0) {
            gxs[w * 4 + i] = s1 * (1.0f / (float)HW);
            gus[w * 4 + i] = s2 * (1.0f / (float)HW);
        }
    }
    __syncthreads();

    // output partial: warp w = class k; lane l = local channel
    {
        const int c = grp * 32 + l;
        float gx = gxs[l];
        float gu = gus[l];
        float val = fmaf(w_cls[w * 2 * C_DIM + c], gx,
                         w_cls[w * 2 * C_DIM + C_DIM + c] * gu);
#pragma unroll
        for (int o = 16; o; o >>= 1)
            val += __shfl_down_sync(0xffffffffu, val, o);
        if (l == 0)
            g_po[((size_t)b * NGRP + grp) * NC + w] = val;
    }
}

// ============================================================================
// K4: output[b,k] = sum_grp po[b,grp,k] + b_cls[k]. grid 128, 256 threads:
// warp w = class k, lanes cover the 64 groups (2 each).
// ============================================================================
__global__ void __launch_bounds__(256) k4_out(
    const float* __restrict__ b_cls,
    float* __restrict__ out_output) {
    const int b = blockIdx.x;
    const int t = threadIdx.x;
    const int w = t >> 5, l = t & 31;

    float v = g_po[((size_t)b * NGRP + l) * NC + w] +
              g_po[((size_t)b * NGRP + l + 32) * NC + w];
#pragma unroll
    for (int o = 16; o; o >>= 1)
        v += __shfl_down_sync(0xffffffffu, v, o);
    if (l == 0)
        out_output[b * NC + w] = v + b_cls[w];
}

// ============================================================================
// Output layout: v[128,8]@0, output[128,8]@1024, m[128,196]@2048,
//                m_c[128,8,196]@27136.
// ============================================================================
extern "C" void kernel_launch(void* const* d_in, const int* in_sizes, int n_in,
                              void* d_out, int out_size) {
    const float* x      = (const float*)d_in[0];
    const float* w_down = (const float*)d_in[1];
    const float* b_down = (const float*)d_in[2];
    const float* w_cls  = (const float*)d_in[3];
    const float* b_cls  = (const float*)d_in[4];

    float* out        = (float*)d_out;
    float* out_v      = out;
    float* out_output = out + 1024;
    float* out_m      = out + 2048;
    float* out_mc     = out + 27136;

    k1_main<<<dim3(PART_N / 256, SLABS), 256>>>(x, w_down);
    k2_epi<<<B_DIM, 224>>>(b_down, out_v, out_m, out_mc);
    k3_gap<<<dim3(NGRP, B_DIM), 256>>>(x, out_m, w_cls);
    k4_out<<<B_DIM, 256>>>(b_cls, out_output);
}